// round 8
// baseline (speedup 1.0000x reference)
#include <cuda_runtime.h>
#include <math.h>
#include <stdint.h>

#define HH 256
#define WW 256
#define BB 4
#define CIN 128
#define NOC 128
#define NSTAGE 24                        // (8 cin-chunks of 16) x (3 dy)

#define A_FLOATS 6144                    // per-stage fragment-permuted A
#define X_FLOATS 2176                    // 16 x 136
#define X_STRIDE 136
#define BUF_BYTES ((A_FLOATS + X_FLOATS) * 4)   // 33280
#define XB_OFF (A_FLOATS * 4)                   // X offset within buffer
#define DYN_BYTES (3 * BUF_BYTES)               // 99840, triple buffer

// xT: per (b, yq=y+dy in 0..257, chunk, half) one contiguous 16x136 tf32 tile
#define XT_PER_ROW 34816                 // 8 chunks * 2 halves * 2176

// ---------------- device scratch ----------------
__device__ float g_wA[NSTAGE * A_FLOATS];
__device__ float g_xT[(size_t)BB * (HH + 2) * XT_PER_ROW];   // 143.7 MB
__device__ float g_bfold[NOC];
__device__ float g_attw[NOC];
__device__ float g_att[2 * BB * HH * WW];

// ---------------- helpers ----------------
__device__ __forceinline__ uint32_t smem_u32(const void* p) {
    uint32_t a;
    asm("{ .reg .u64 t; cvta.to.shared.u64 t, %1; cvt.u32.u64 %0, t; }" : "=r"(a) : "l"(p));
    return a;
}
__device__ __forceinline__ uint32_t f2tf32(float f) {
    uint32_t r; asm("cvt.rna.tf32.f32 %0, %1;" : "=r"(r) : "f"(f)); return r;
}
__device__ __forceinline__ void cp16(uint32_t dst, const void* src) {
    asm volatile("cp.async.cg.shared.global [%0], [%1], 16;" :: "r"(dst), "l"(src));
}
__device__ __forceinline__ void mma8(float* d, const uint32_t* a, uint32_t b0, uint32_t b1) {
    asm volatile(
        "mma.sync.aligned.m16n8k8.row.col.f32.tf32.tf32.f32 "
        "{%0,%1,%2,%3},{%4,%5,%6,%7},{%8,%9},{%0,%1,%2,%3};"
        : "+f"(d[0]), "+f"(d[1]), "+f"(d[2]), "+f"(d[3])
        : "r"(a[0]), "r"(a[1]), "r"(a[2]), "r"(a[3]), "r"(b0), "r"(b1));
}

// ---------------- kernel 0: BN fold + fragment-permuted tf32 weight tiles ----------------
__global__ void setup_kernel(
    const float* __restrict__ wa, const float* __restrict__ ba,
    const float* __restrict__ wb, const float* __restrict__ bb,
    const float* __restrict__ ga, const float* __restrict__ bta,
    const float* __restrict__ ma, const float* __restrict__ va,
    const float* __restrict__ gb, const float* __restrict__ btb,
    const float* __restrict__ mb, const float* __restrict__ vb,
    const float* __restrict__ attaw, const float* __restrict__ attbw)
{
    int idx = blockIdx.x * blockDim.x + threadIdx.x;
    if (idx < NOC) {
        int oc = idx;
        bool isa = oc < 64;
        int o = isa ? oc : oc - 64;
        float gamma = isa ? ga[o] : gb[o];
        float beta  = isa ? bta[o] : btb[o];
        float mean  = isa ? ma[o] : mb[o];
        float var   = isa ? va[o] : vb[o];
        float A = gamma / sqrtf(var + 1e-3f);
        float bias = isa ? ba[o] : bb[o];
        g_bfold[oc] = (bias - mean) * A + beta;
        g_attw[oc]  = isa ? attaw[o] : attbw[o];
    }
    if (idx < NSTAGE * A_FLOATS) {
        int e    = idx & 3;
        int lane = (idx >> 2) & 31;
        int blk  = (idx >> 7) & 7;
        int kc   = (idx >> 10) % 6;
        int s    = idx / A_FLOATS;
        int g    = lane >> 2;
        int tig  = lane & 3;
        int oc = blk * 16 + g + ((e & 1) ? 8 : 0);
        int kl = tig + ((e & 2) ? 4 : 0);
        int cl = (kc & 1) * 8 + kl;
        int dxi = kc >> 1;
        int cin = (s / 3) * 16 + cl;
        int dy  = s % 3;
        bool isa = oc < 64;
        int o = isa ? oc : oc - 64;
        float gamma = isa ? ga[o] : gb[o];
        float var   = isa ? va[o] : vb[o];
        float A = gamma / sqrtf(var + 1e-3f);
        const float* w = isa ? wa : wb;
        float v = w[((o * CIN + cin) * 3 + dy) * 3 + dxi] * A;
        g_wA[idx] = __uint_as_float(f2tf32(v));
    }
}

// ---------------- kernel 0b: x -> tf32 pre-staged smem image ----------------
// grid (136, BB*(HH+2)); idx over [chunk][half][ci][j=0..135]
__global__ void __launch_bounds__(256) prep_x_kernel(const float* __restrict__ x)
{
    int idx = blockIdx.x * 256 + threadIdx.x;     // 0..34815
    int row = blockIdx.y;                         // b*258 + yq
    int b  = row / (HH + 2);
    int yq = row % (HH + 2);
    int j    = idx % 136;
    int rest = idx / 136;
    int ci   = rest & 15;
    int half = (rest >> 4) & 1;
    int chunk = rest >> 5;
    int y   = yq - 1;
    int col = half * 128 - 1 + j;
    float v = 0.f;
    if ((unsigned)y < HH && (unsigned)col < WW && j < 130)
        v = x[(((size_t)b * CIN + chunk * 16 + ci) * HH + y) * WW + col];
    g_xT[(size_t)row * XT_PER_ROW + idx] = __uint_as_float(f2tf32(v));
}

// ---------------- kernel 1: mma.sync tf32 conv + BN + 1x1 attention logit ----------------
// grid (2, 256, 4) = (col half, row y, batch). 256 threads, 8 warps, 2 CTAs/SM.
__global__ void __launch_bounds__(256, 2) conv_att_kernel(
    float* __restrict__ out,
    const float* __restrict__ attaw, const float* __restrict__ attab,
    const float* __restrict__ attbw, const float* __restrict__ attbb,
    const float* __restrict__ abga, const float* __restrict__ abba,
    const float* __restrict__ abma, const float* __restrict__ abva,
    const float* __restrict__ abgb, const float* __restrict__ abbb,
    const float* __restrict__ abmb, const float* __restrict__ abvb)
{
    extern __shared__ __align__(16) char dyn[];
    const int tid  = threadIdx.x;
    const int b    = blockIdx.z;
    const int y    = blockIdx.y;
    const int half = blockIdx.x;
    const int c0   = half * 128;
    const int w    = tid >> 5;
    const int lane = tid & 31;
    const int g    = lane >> 2;
    const int tig  = lane & 3;
    const int oc0  = (w >> 1) * 32;
    const int pix0 = (w & 1) * 64;
    const int blk0 = (w >> 1) * 2;
    const uint32_t dynb = smem_u32(dyn);

    float c[2][8][4];
    #pragma unroll
    for (int mm = 0; mm < 2; mm++)
        #pragma unroll
        for (int nn = 0; nn < 8; nn++)
            #pragma unroll
            for (int k = 0; k < 4; k++) c[mm][nn][k] = 0.f;

    // stage-issue: A (24576 B) + X (8704 B) via cp.async, then commit (possibly empty)
    auto stage_issue = [&](int s, int p) {
        if (s < NSTAGE) {
            const char* asrc = (const char*)(g_wA + (size_t)s * A_FLOATS) + tid * 16;
            uint32_t ad = dynb + p * BUF_BYTES + tid * 16;
            #pragma unroll
            for (int r = 0; r < 6; r++)
                cp16(ad + r * 4096, asrc + r * 4096);
            const int yq = y + s % 3;    // 0..257
            const char* xsrc = (const char*)(g_xT
                + (size_t)(b * (HH + 2) + yq) * XT_PER_ROW
                + (size_t)((s / 3) * 2 + half) * X_FLOATS) + tid * 16;
            uint32_t xd = dynb + p * BUF_BYTES + XB_OFF + tid * 16;
            cp16(xd, xsrc);
            cp16(xd + 4096, xsrc + 4096);
            if (tid < 32) cp16(xd + 8192, xsrc + 8192);
        }
        asm volatile("cp.async.commit_group;" ::: "memory");
    };

    stage_issue(0, 0);
    stage_issue(1, 1);

    for (int s = 0; s < NSTAGE; s++) {
        const int p = s % 3;
        asm volatile("cp.async.wait_group 1;" ::: "memory");
        __syncthreads();
        stage_issue(s + 2, (s + 2) % 3);

        const float4* As = (const float4*)(dyn + p * BUF_BYTES);
        const float* Xs = (const float*)(dyn + p * BUF_BYTES + XB_OFF);
        #pragma unroll
        for (int kc = 0; kc < 6; kc++) {
            const int dxi = kc >> 1;
            const int c0k = (kc & 1) * 8;
            uint32_t a[2][4];
            #pragma unroll
            for (int mm = 0; mm < 2; mm++) {
                float4 av = As[(kc * 8 + blk0 + mm) * 32 + lane];
                a[mm][0] = __float_as_uint(av.x);
                a[mm][1] = __float_as_uint(av.y);
                a[mm][2] = __float_as_uint(av.z);
                a[mm][3] = __float_as_uint(av.w);
            }
            #pragma unroll
            for (int nn = 0; nn < 8; nn++) {
                const float* bp = Xs + (c0k + tig) * X_STRIDE + pix0 + nn * 8 + g + dxi;
                uint32_t b0 = __float_as_uint(bp[0]);
                uint32_t b1 = __float_as_uint(bp[4 * X_STRIDE]);
                mma8(c[0][nn], a[0], b0, b1);
                mma8(c[1][nn], a[1], b0, b1);
            }
        }
    }

    // ---------------- epilogue ----------------
    float bf[2][2], aw[2][2];
    #pragma unroll
    for (int mm = 0; mm < 2; mm++)
        #pragma unroll
        for (int i2 = 0; i2 < 2; i2++) {
            int ocr = oc0 + mm * 16 + g + i2 * 8;
            bf[mm][i2] = g_bfold[ocr];
            aw[mm][i2] = g_attw[ocr];
        }

    float ap_loc[8][2];
    #pragma unroll
    for (int nn = 0; nn < 8; nn++) { ap_loc[nn][0] = 0.f; ap_loc[nn][1] = 0.f; }

    #pragma unroll
    for (int mm = 0; mm < 2; mm++)
        #pragma unroll
        for (int i2 = 0; i2 < 2; i2++) {
            int ocr = oc0 + mm * 16 + g + i2 * 8;
            float* orow = out + (((size_t)b * NOC + ocr) * HH + y) * WW + c0 + pix0 + 2 * tig;
            #pragma unroll
            for (int nn = 0; nn < 8; nn++) {
                float f0 = c[mm][nn][i2 * 2 + 0] + bf[mm][i2];
                float f1 = c[mm][nn][i2 * 2 + 1] + bf[mm][i2];
                ap_loc[nn][0] = fmaf(aw[mm][i2], f0, ap_loc[nn][0]);
                ap_loc[nn][1] = fmaf(aw[mm][i2], f1, ap_loc[nn][1]);
                *(float2*)(orow + nn * 8) = make_float2(f0, f1);
            }
        }

    // reduce attention partials over g-lanes (same tig), deterministic butterfly
    #pragma unroll
    for (int nn = 0; nn < 8; nn++)
        #pragma unroll
        for (int j = 0; j < 2; j++) {
            float v = ap_loc[nn][j];
            v += __shfl_xor_sync(0xFFFFFFFF, v, 4);
            v += __shfl_xor_sync(0xFFFFFFFF, v, 8);
            v += __shfl_xor_sync(0xFFFFFFFF, v, 16);
            ap_loc[nn][j] = v;
        }
    float* att_part = (float*)dyn;   // buf0 region: last read at stage 21, safe now
    if (g == 0) {
        #pragma unroll
        for (int nn = 0; nn < 8; nn++) {
            att_part[w * 64 + nn * 8 + 2 * tig + 0] = ap_loc[nn][0];
            att_part[w * 64 + nn * 8 + 2 * tig + 1] = ap_loc[nn][1];
        }
    }
    __syncthreads();

    {
        int branch = tid >> 7;
        int pix = tid & 127;
        int nh = pix >> 6, pl = pix & 63;
        float ssum = att_part[(4 * branch + nh) * 64 + pl]
                   + att_part[(4 * branch + 2 + nh) * 64 + pl];
        int xx = c0 + pix;
        float gh = fabsf((float)y  - 127.5f) * (1.f / 128.f);
        float gw = fabsf((float)xx - 127.5f) * (1.f / 128.f);
        const float* awp = branch ? attbw : attaw;
        float pre = ssum + awp[64] * gh + awp[65] * gw + (branch ? attbb[0] : attab[0]);
        float gm = branch ? abgb[0] : abga[0];
        float bt = branch ? abbb[0] : abba[0];
        float mn = branch ? abmb[0] : abma[0];
        float vr = branch ? abvb[0] : abva[0];
        float av = (pre - mn) * gm / sqrtf(vr + 1e-5f) + bt;
        g_att[(((size_t)branch * BB + b) * HH + y) * WW + xx] = av;
    }
}

// ---------------- kernel 2: 3x3 attention conv + sigmoid + in-place gating ----------------
__global__ void __launch_bounds__(256) map_kernel(
    float* __restrict__ out,
    const float* __restrict__ wa, const float* __restrict__ wb,
    const float* __restrict__ s1, const float* __restrict__ s2)
{
    __shared__ float swa[36], swb[36];
    int t = threadIdx.y * 32 + threadIdx.x;
    if (t < 36) { swa[t] = wa[t]; swb[t] = wb[t]; }
    __syncthreads();

    int b   = blockIdx.z;
    int gy  = blockIdx.y * 8 + threadIdx.y;
    int gx4 = blockIdx.x * 128 + threadIdx.x * 4;

    const float prmax = 1.41421356237f * (127.5f / 128.f);
    const float prmin = 1.41421356237f * (0.5f / 128.f);
    const float prk = 2.f / (prmax - prmin);
    const float prc = 1.f - prmax * prk;

    float scl1 = s1[0], scl2 = s2[0];
    float mapa[4], mapb[4];
    #pragma unroll
    for (int p = 0; p < 4; p++) {
        int gx = gx4 + p;
        float sa = 0.f, sb = 0.f;
        #pragma unroll
        for (int rr = 0; rr < 3; rr++) {
            int yq = gy + rr - 1;
            if ((unsigned)yq >= HH) continue;
            #pragma unroll
            for (int ss = 0; ss < 3; ss++) {
                int xq = gx + ss - 1;
                if ((unsigned)xq >= WW) continue;
                float av = g_att[(((size_t)0 * BB + b) * HH + yq) * WW + xq];
                float bv = g_att[(((size_t)1 * BB + b) * HH + yq) * WW + xq];
                float gh = fabsf((float)yq - 127.5f) * (1.f / 128.f);
                float gw = fabsf((float)xq - 127.5f) * (1.f / 128.f);
                float pr = prk * sqrtf(gh * gh + gw * gw) + prc;
                int tap = rr * 3 + ss;
                sa += swa[tap] * av + swa[9 + tap] * gh + swa[18 + tap] * gw + swa[27 + tap] * pr;
                sb += swb[tap] * bv + swb[9 + tap] * gh + swb[18 + tap] * gw + swb[27 + tap] * pr;
            }
        }
        mapa[p] = scl1 / (1.f + expf(-sa));
        mapb[p] = scl2 / (1.f + expf(-sb));
    }

    size_t base = (((size_t)b * NOC) * HH + gy) * WW + gx4;
    #pragma unroll 4
    for (int oc = 0; oc < NOC; oc++) {
        float4 v = *(float4*)(out + base + (size_t)oc * HH * WW);
        if (oc < 64) { v.x *= mapa[0]; v.y *= mapa[1]; v.z *= mapa[2]; v.w *= mapa[3]; }
        else         { v.x *= mapb[0]; v.y *= mapb[1]; v.z *= mapb[2]; v.w *= mapb[3]; }
        *(float4*)(out + base + (size_t)oc * HH * WW) = v;
    }
}

// ---------------- launch ----------------
extern "C" void kernel_launch(void* const* d_in, const int* in_sizes, int n_in,
                              void* d_out, int out_size)
{
    const float* x     = (const float*)d_in[0];
    const float* caw   = (const float*)d_in[1];
    const float* cab   = (const float*)d_in[2];
    const float* cbw   = (const float*)d_in[3];
    const float* cbb   = (const float*)d_in[4];
    const float* bag   = (const float*)d_in[5];
    const float* babt  = (const float*)d_in[6];
    const float* bam   = (const float*)d_in[7];
    const float* bav   = (const float*)d_in[8];
    const float* bbg   = (const float*)d_in[9];
    const float* bbbt  = (const float*)d_in[10];
    const float* bbm   = (const float*)d_in[11];
    const float* bbv   = (const float*)d_in[12];
    const float* attaw = (const float*)d_in[13];
    const float* attab = (const float*)d_in[14];
    const float* attbw = (const float*)d_in[15];
    const float* attbb = (const float*)d_in[16];
    const float* abga  = (const float*)d_in[17];
    const float* abba  = (const float*)d_in[18];
    const float* abma  = (const float*)d_in[19];
    const float* abva  = (const float*)d_in[20];
    const float* abgb  = (const float*)d_in[21];
    const float* abbb  = (const float*)d_in[22];
    const float* abmb  = (const float*)d_in[23];
    const float* abvb  = (const float*)d_in[24];
    const float* anaw  = (const float*)d_in[25];
    const float* anbw  = (const float*)d_in[26];
    const float* s1    = (const float*)d_in[27];
    const float* s2    = (const float*)d_in[28];
    float* out = (float*)d_out;

    cudaFuncSetAttribute(conv_att_kernel,
                         cudaFuncAttributeMaxDynamicSharedMemorySize, DYN_BYTES);

    setup_kernel<<<(NSTAGE * A_FLOATS + 255) / 256, 256>>>(
        caw, cab, cbw, cbb,
        bag, babt, bam, bav, bbg, bbbt, bbm, bbv,
        attaw, attbw);

    prep_x_kernel<<<dim3(136, BB * (HH + 2)), 256>>>(x);

    conv_att_kernel<<<dim3(2, HH, BB), 256, DYN_BYTES>>>(
        out, attaw, attab, attbw, attbb,
        abga, abba, abma, abva, abgb, abbb, abmb, abvb);

    map_kernel<<<dim3(WW / 128, HH / 8, BB), dim3(32, 8)>>>(
        out, anaw, anbw, s1, s2);
}

// round 10
// speedup vs baseline: 1.1323x; 1.1323x over previous
#include <cuda_runtime.h>
#include <math.h>
#include <stdint.h>

#define HH 256
#define WW 256
#define BB 4
#define CIN 128
#define NOC 128
#define NSTAGE 24                        // (8 cin-chunks of 16) x (3 dy)

#define A_FLOATS 6144                    // per-stage fragment-permuted A
#define X_STRIDE 136
#define X_FLOATS (16 * X_STRIDE)         // 2176
#define AOFF(p) ((p) * A_FLOATS * 4)
#define XOFF(p) (2 * A_FLOATS * 4 + (p) * X_FLOATS * 4)
#define DYN_BYTES (2 * A_FLOATS * 4 + 2 * X_FLOATS * 4)   // 66560

// ---------------- device scratch ----------------
__device__ float g_wA[NSTAGE * A_FLOATS]; // fragment-permuted, tf32-rounded, BN-folded
__device__ float g_bfold[NOC];
__device__ float g_attw[NOC];
__device__ float g_att[2 * BB * HH * WW];

// ---------------- helpers ----------------
__device__ __forceinline__ uint32_t smem_u32(const void* p) {
    uint32_t a;
    asm("{ .reg .u64 t; cvta.to.shared.u64 t, %1; cvt.u32.u64 %0, t; }" : "=r"(a) : "l"(p));
    return a;
}
__device__ __forceinline__ uint32_t f2tf32(float f) {
    uint32_t r; asm("cvt.rna.tf32.f32 %0, %1;" : "=r"(r) : "f"(f)); return r;
}
__device__ __forceinline__ void cp16(uint32_t dst, const void* src) {
    asm volatile("cp.async.cg.shared.global [%0], [%1], 16;" :: "r"(dst), "l"(src));
}
__device__ __forceinline__ void mma8(float* d, const uint32_t* a, uint32_t b0, uint32_t b1) {
    asm volatile(
        "mma.sync.aligned.m16n8k8.row.col.f32.tf32.tf32.f32 "
        "{%0,%1,%2,%3},{%4,%5,%6,%7},{%8,%9},{%0,%1,%2,%3};"
        : "+f"(d[0]), "+f"(d[1]), "+f"(d[2]), "+f"(d[3])
        : "r"(a[0]), "r"(a[1]), "r"(a[2]), "r"(a[3]), "r"(b0), "r"(b1));
}

// ---------------- kernel 0: BN fold + fragment-permuted tf32 weight tiles ----------------
__global__ void setup_kernel(
    const float* __restrict__ wa, const float* __restrict__ ba,
    const float* __restrict__ wb, const float* __restrict__ bb,
    const float* __restrict__ ga, const float* __restrict__ bta,
    const float* __restrict__ ma, const float* __restrict__ va,
    const float* __restrict__ gb, const float* __restrict__ btb,
    const float* __restrict__ mb, const float* __restrict__ vb,
    const float* __restrict__ attaw, const float* __restrict__ attbw)
{
    int idx = blockIdx.x * blockDim.x + threadIdx.x;
    if (idx < NOC) {
        int oc = idx;
        bool isa = oc < 64;
        int o = isa ? oc : oc - 64;
        float gamma = isa ? ga[o] : gb[o];
        float beta  = isa ? bta[o] : btb[o];
        float mean  = isa ? ma[o] : mb[o];
        float var   = isa ? va[o] : vb[o];
        float A = gamma / sqrtf(var + 1e-3f);
        float bias = isa ? ba[o] : bb[o];
        g_bfold[oc] = (bias - mean) * A + beta;
        g_attw[oc]  = isa ? attaw[o] : attbw[o];
    }
    if (idx < NSTAGE * A_FLOATS) {
        int e    = idx & 3;
        int lane = (idx >> 2) & 31;
        int blk  = (idx >> 7) & 7;
        int kc   = (idx >> 10) % 6;
        int s    = idx / A_FLOATS;
        int g    = lane >> 2;
        int tig  = lane & 3;
        int oc = blk * 16 + g + ((e & 1) ? 8 : 0);
        int kl = tig + ((e & 2) ? 4 : 0);
        int cl = (kc & 1) * 8 + kl;
        int dxi = kc >> 1;
        int cin = (s / 3) * 16 + cl;
        int dy  = s % 3;
        bool isa = oc < 64;
        int o = isa ? oc : oc - 64;
        float gamma = isa ? ga[o] : gb[o];
        float var   = isa ? va[o] : vb[o];
        float A = gamma / sqrtf(var + 1e-3f);
        const float* w = isa ? wa : wb;
        float v = w[((o * CIN + cin) * 3 + dy) * 3 + dxi] * A;
        g_wA[idx] = __uint_as_float(f2tf32(v));
    }
}

// ---------------- kernel 1: mma.sync tf32 conv + BN + 1x1 attention logit ----------------
// grid (2, 256, 4) = (col half, row y, batch). 256 threads, 8 warps, 2 CTAs/SM.
// warp w: oc0 = (w>>1)*32, pix0 = (w&1)*64. D = 128oc x 128pix, K = 24 stages x 48.
__global__ void __launch_bounds__(256, 2) conv_att_kernel(
    const float* __restrict__ x, float* __restrict__ out,
    const float* __restrict__ attaw, const float* __restrict__ attab,
    const float* __restrict__ attbw, const float* __restrict__ attbb,
    const float* __restrict__ abga, const float* __restrict__ abba,
    const float* __restrict__ abma, const float* __restrict__ abva,
    const float* __restrict__ abgb, const float* __restrict__ abbb,
    const float* __restrict__ abmb, const float* __restrict__ abvb)
{
    extern __shared__ __align__(16) char dyn[];
    const int tid  = threadIdx.x;
    const int b    = blockIdx.z;
    const int y    = blockIdx.y;
    const int c0   = blockIdx.x * 128;
    const int w    = tid >> 5;
    const int lane = tid & 31;
    const int g    = lane >> 2;
    const int tig  = lane & 3;
    const int oc0  = (w >> 1) * 32;
    const int pix0 = (w & 1) * 64;
    const int blk0 = (w >> 1) * 2;
    const uint32_t dynb = smem_u32(dyn);

    float c[2][8][4];
    #pragma unroll
    for (int mm = 0; mm < 2; mm++)
        #pragma unroll
        for (int nn = 0; nn < 8; nn++)
            #pragma unroll
            for (int k = 0; k < 4; k++) c[mm][nn][k] = 0.f;

    const int cc = tid >> 4, l16 = tid & 15;   // x staging: 16 rows x 16 threads

    // ---- prologue: stage s=0 into buffer 0 ----
    {
        const char* src = (const char*)(g_wA) + tid * 16;
        #pragma unroll
        for (int r = 0; r < 6; r++)
            cp16(dynb + AOFF(0) + tid * 16 + r * 4096, src + r * 4096);
        asm volatile("cp.async.commit_group;" ::: "memory");

        float xr[9];
        int grow = y - 1;
        if ((unsigned)grow < HH) {
            const float* xb = x + (((size_t)b * CIN + cc) * HH + grow) * WW;
            #pragma unroll
            for (int i = 0; i < 9; i++) {
                int j = l16 + i * 16;
                int col = c0 - 1 + j;
                xr[i] = (j < 130 && (unsigned)col < WW) ? xb[col] : 0.f;
            }
        } else {
            #pragma unroll
            for (int i = 0; i < 9; i++) xr[i] = 0.f;
        }
        float* Xs = (float*)(dyn + XOFF(0));
        #pragma unroll
        for (int i = 0; i < 9; i++) {
            int j = l16 + i * 16;
            if (j < 130) Xs[cc * X_STRIDE + j] = __uint_as_float(f2tf32(xr[i]));
        }
        asm volatile("cp.async.wait_group 0;" ::: "memory");
        __syncthreads();
    }

    // ---- main loop ----
    for (int s = 0; s < NSTAGE; s++) {
        const int p = s & 1;
        const bool pre = (s + 1 < NSTAGE);
        float xr[9];

        if (pre) {
            const char* src = (const char*)(g_wA + (s + 1) * A_FLOATS) + tid * 16;
            #pragma unroll
            for (int r = 0; r < 6; r++)
                cp16(dynb + AOFF(p ^ 1) + tid * 16 + r * 4096, src + r * 4096);
            asm volatile("cp.async.commit_group;" ::: "memory");
            int sn = s + 1;
            int grow = y + (sn % 3) - 1;
            if ((unsigned)grow < HH) {
                const float* xb = x + (((size_t)b * CIN + (sn / 3) * 16 + cc) * HH + grow) * WW;
                #pragma unroll
                for (int i = 0; i < 9; i++) {
                    int j = l16 + i * 16;
                    int col = c0 - 1 + j;
                    xr[i] = (j < 130 && (unsigned)col < WW) ? xb[col] : 0.f;
                }
            } else {
                #pragma unroll
                for (int i = 0; i < 9; i++) xr[i] = 0.f;
            }
        }

        // ---- compute on buffer p ----
        {
            const float4* As = (const float4*)(dyn + AOFF(p));
            const float* Xs = (const float*)(dyn + XOFF(p));
            #pragma unroll
            for (int kc = 0; kc < 6; kc++) {
                const int dxi = kc >> 1;
                const int c0k = (kc & 1) * 8;
                uint32_t a[2][4];
                #pragma unroll
                for (int mm = 0; mm < 2; mm++) {
                    float4 av = As[(kc * 8 + blk0 + mm) * 32 + lane];
                    a[mm][0] = __float_as_uint(av.x);
                    a[mm][1] = __float_as_uint(av.y);
                    a[mm][2] = __float_as_uint(av.z);
                    a[mm][3] = __float_as_uint(av.w);
                }
                #pragma unroll
                for (int nn = 0; nn < 8; nn++) {
                    const float* bp = Xs + (c0k + tig) * X_STRIDE + pix0 + nn * 8 + g + dxi;
                    uint32_t b0 = __float_as_uint(bp[0]);
                    uint32_t b1 = __float_as_uint(bp[4 * X_STRIDE]);
                    mma8(c[0][nn], a[0], b0, b1);
                    mma8(c[1][nn], a[1], b0, b1);
                }
            }
        }

        if (pre) {
            float* Xs = (float*)(dyn + XOFF(p ^ 1));
            #pragma unroll
            for (int i = 0; i < 9; i++) {
                int j = l16 + i * 16;
                if (j < 130) Xs[cc * X_STRIDE + j] = __uint_as_float(f2tf32(xr[i]));
            }
        }
        asm volatile("cp.async.wait_group 0;" ::: "memory");
        __syncthreads();
    }

    // ---------------- epilogue ----------------
    float bf[2][2], aw[2][2];
    #pragma unroll
    for (int mm = 0; mm < 2; mm++)
        #pragma unroll
        for (int i2 = 0; i2 < 2; i2++) {
            int ocr = oc0 + mm * 16 + g + i2 * 8;
            bf[mm][i2] = g_bfold[ocr];
            aw[mm][i2] = g_attw[ocr];
        }

    float ap_loc[8][2];
    #pragma unroll
    for (int nn = 0; nn < 8; nn++) { ap_loc[nn][0] = 0.f; ap_loc[nn][1] = 0.f; }

    #pragma unroll
    for (int mm = 0; mm < 2; mm++)
        #pragma unroll
        for (int i2 = 0; i2 < 2; i2++) {
            int ocr = oc0 + mm * 16 + g + i2 * 8;
            float* orow = out + (((size_t)b * NOC + ocr) * HH + y) * WW + c0 + pix0 + 2 * tig;
            #pragma unroll
            for (int nn = 0; nn < 8; nn++) {
                float f0 = c[mm][nn][i2 * 2 + 0] + bf[mm][i2];
                float f1 = c[mm][nn][i2 * 2 + 1] + bf[mm][i2];
                ap_loc[nn][0] = fmaf(aw[mm][i2], f0, ap_loc[nn][0]);
                ap_loc[nn][1] = fmaf(aw[mm][i2], f1, ap_loc[nn][1]);
                *(float2*)(orow + nn * 8) = make_float2(f0, f1);
            }
        }

    // reduce attention partials over g-lanes (same tig), deterministic butterfly
    #pragma unroll
    for (int nn = 0; nn < 8; nn++)
        #pragma unroll
        for (int j = 0; j < 2; j++) {
            float v = ap_loc[nn][j];
            v += __shfl_xor_sync(0xFFFFFFFF, v, 4);
            v += __shfl_xor_sync(0xFFFFFFFF, v, 8);
            v += __shfl_xor_sync(0xFFFFFFFF, v, 16);
            ap_loc[nn][j] = v;
        }
    float* att_part = (float*)dyn;   // A buf0 region, free now
    if (g == 0) {
        #pragma unroll
        for (int nn = 0; nn < 8; nn++) {
            att_part[w * 64 + nn * 8 + 2 * tig + 0] = ap_loc[nn][0];
            att_part[w * 64 + nn * 8 + 2 * tig + 1] = ap_loc[nn][1];
        }
    }
    __syncthreads();

    {
        int branch = tid >> 7;
        int pix = tid & 127;
        int nh = pix >> 6, pl = pix & 63;
        float ssum = att_part[(4 * branch + nh) * 64 + pl]
                   + att_part[(4 * branch + 2 + nh) * 64 + pl];
        int xx = c0 + pix;
        float gh = fabsf((float)y  - 127.5f) * (1.f / 128.f);
        float gw = fabsf((float)xx - 127.5f) * (1.f / 128.f);
        const float* awp = branch ? attbw : attaw;
        float pre = ssum + awp[64] * gh + awp[65] * gw + (branch ? attbb[0] : attab[0]);
        float gm = branch ? abgb[0] : abga[0];
        float bt = branch ? abbb[0] : abba[0];
        float mn = branch ? abmb[0] : abma[0];
        float vr = branch ? abvb[0] : abva[0];
        float av = (pre - mn) * gm / sqrtf(vr + 1e-5f) + bt;
        g_att[(((size_t)branch * BB + b) * HH + y) * WW + xx] = av;
    }
}

// ---------------- kernel 2: 3x3 attention conv + sigmoid + in-place gating ----------------
// grid (2, 32*4, BB): x = col half, y = (row-block 0..31)*4 + oc-chunk, z = b.
// Each block: 8 rows x 128 cols x 32 oc. Maps recomputed per oc-chunk (cheap).
__global__ void __launch_bounds__(256) map_kernel(
    float* __restrict__ out,
    const float* __restrict__ wa, const float* __restrict__ wb,
    const float* __restrict__ s1, const float* __restrict__ s2)
{
    __shared__ float swa[36], swb[36];
    int tx = threadIdx.x & 31, ty = threadIdx.x >> 5;
    int t = threadIdx.x;
    if (t < 36) { swa[t] = wa[t]; swb[t] = wb[t]; }
    __syncthreads();

    int b    = blockIdx.z;
    int gy   = (blockIdx.y >> 2) * 8 + ty;
    int occ0 = (blockIdx.y & 3) * 32;
    int gx4  = blockIdx.x * 128 + tx * 4;

    const float prmax = 1.41421356237f * (127.5f / 128.f);
    const float prmin = 1.41421356237f * (0.5f / 128.f);
    const float prk = 2.f / (prmax - prmin);
    const float prc = 1.f - prmax * prk;

    float scl1 = s1[0], scl2 = s2[0];
    bool isa = occ0 < 64;
    const float* sw = isa ? swa : swb;
    const float* gatt = g_att + (isa ? 0 : (size_t)BB * HH * WW);
    float scl = isa ? scl1 : scl2;

    float mp[4];
    #pragma unroll
    for (int p = 0; p < 4; p++) {
        int gx = gx4 + p;
        float sa = 0.f;
        #pragma unroll
        for (int rr = 0; rr < 3; rr++) {
            int yq = gy + rr - 1;
            if ((unsigned)yq >= HH) continue;
            #pragma unroll
            for (int ss = 0; ss < 3; ss++) {
                int xq = gx + ss - 1;
                if ((unsigned)xq >= WW) continue;
                float av = gatt[((size_t)b * HH + yq) * WW + xq];
                float gh = fabsf((float)yq - 127.5f) * (1.f / 128.f);
                float gw = fabsf((float)xq - 127.5f) * (1.f / 128.f);
                float pr = prk * sqrtf(gh * gh + gw * gw) + prc;
                int tap = rr * 3 + ss;
                sa += sw[tap] * av + sw[9 + tap] * gh + sw[18 + tap] * gw + sw[27 + tap] * pr;
            }
        }
        mp[p] = scl / (1.f + expf(-sa));
    }

    size_t base = (((size_t)b * NOC + occ0) * HH + gy) * WW + gx4;
    #pragma unroll 4
    for (int oc = 0; oc < 32; oc++) {
        float4 v = *(float4*)(out + base + (size_t)oc * HH * WW);
        v.x *= mp[0]; v.y *= mp[1]; v.z *= mp[2]; v.w *= mp[3];
        *(float4*)(out + base + (size_t)oc * HH * WW) = v;
    }
}

// ---------------- launch ----------------
extern "C" void kernel_launch(void* const* d_in, const int* in_sizes, int n_in,
                              void* d_out, int out_size)
{
    const float* x     = (const float*)d_in[0];
    const float* caw   = (const float*)d_in[1];
    const float* cab   = (const float*)d_in[2];
    const float* cbw   = (const float*)d_in[3];
    const float* cbb   = (const float*)d_in[4];
    const float* bag   = (const float*)d_in[5];
    const float* babt  = (const float*)d_in[6];
    const float* bam   = (const float*)d_in[7];
    const float* bav   = (const float*)d_in[8];
    const float* bbg   = (const float*)d_in[9];
    const float* bbbt  = (const float*)d_in[10];
    const float* bbm   = (const float*)d_in[11];
    const float* bbv   = (const float*)d_in[12];
    const float* attaw = (const float*)d_in[13];
    const float* attab = (const float*)d_in[14];
    const float* attbw = (const float*)d_in[15];
    const float* attbb = (const float*)d_in[16];
    const float* abga  = (const float*)d_in[17];
    const float* abba  = (const float*)d_in[18];
    const float* abma  = (const float*)d_in[19];
    const float* abva  = (const float*)d_in[20];
    const float* abgb  = (const float*)d_in[21];
    const float* abbb  = (const float*)d_in[22];
    const float* abmb  = (const float*)d_in[23];
    const float* abvb  = (const float*)d_in[24];
    const float* anaw  = (const float*)d_in[25];
    const float* anbw  = (const float*)d_in[26];
    const float* s1    = (const float*)d_in[27];
    const float* s2    = (const float*)d_in[28];
    float* out = (float*)d_out;

    cudaFuncSetAttribute(conv_att_kernel,
                         cudaFuncAttributeMaxDynamicSharedMemorySize, DYN_BYTES);

    setup_kernel<<<(NSTAGE * A_FLOATS + 255) / 256, 256>>>(
        caw, cab, cbw, cbb,
        bag, babt, bam, bav, bbg, bbbt, bbm, bbv,
        attaw, attbw);

    conv_att_kernel<<<dim3(2, HH, BB), 256, DYN_BYTES>>>(
        x, out, attaw, attab, attbw, attbb,
        abga, abba, abma, abva, abgb, abbb, abmb, abvb);

    map_kernel<<<dim3(2, 32 * 4, BB), 256>>>(
        out, anaw, anbw, s1, s2);
}

// round 11
// speedup vs baseline: 1.1333x; 1.0009x over previous
#include <cuda_runtime.h>
#include <math.h>
#include <stdint.h>

#define HH 256
#define WW 256
#define BB 4
#define CIN 128
#define NOC 128
#define NSTAGE 24                        // (8 cin-chunks of 16) x (3 dy)

#define A_FLOATS 6144                    // per-stage fragment-permuted A
#define X_STRIDE 136
#define X_FLOATS (16 * X_STRIDE)         // 2176
#define AOFF(p) ((p) * A_FLOATS * 4)
#define XOFF(p) (2 * A_FLOATS * 4 + (p) * X_FLOATS * 4)
#define DYN_BYTES (2 * A_FLOATS * 4 + 2 * X_FLOATS * 4)   // 66560

// ---------------- device scratch ----------------
__device__ float g_wA[NSTAGE * A_FLOATS]; // fragment-permuted, tf32-rounded, BN-folded
__device__ float g_bfold[NOC];
__device__ float g_attw[NOC];
__device__ float g_att[2 * BB * HH * WW];

// ---------------- helpers ----------------
__device__ __forceinline__ uint32_t smem_u32(const void* p) {
    uint32_t a;
    asm("{ .reg .u64 t; cvta.to.shared.u64 t, %1; cvt.u32.u64 %0, t; }" : "=r"(a) : "l"(p));
    return a;
}
__device__ __forceinline__ uint32_t f2tf32(float f) {
    uint32_t r; asm("cvt.rna.tf32.f32 %0, %1;" : "=r"(r) : "f"(f)); return r;
}
__device__ __forceinline__ void cp16(uint32_t dst, const void* src) {
    asm volatile("cp.async.cg.shared.global [%0], [%1], 16;" :: "r"(dst), "l"(src));
}
__device__ __forceinline__ void mma8(float* d, const uint32_t* a, uint32_t b0, uint32_t b1) {
    asm volatile(
        "mma.sync.aligned.m16n8k8.row.col.f32.tf32.tf32.f32 "
        "{%0,%1,%2,%3},{%4,%5,%6,%7},{%8,%9},{%0,%1,%2,%3};"
        : "+f"(d[0]), "+f"(d[1]), "+f"(d[2]), "+f"(d[3])
        : "r"(a[0]), "r"(a[1]), "r"(a[2]), "r"(a[3]), "r"(b0), "r"(b1));
}

// ---------------- kernel 0: BN fold + fragment-permuted tf32 weight tiles ----------------
__global__ void setup_kernel(
    const float* __restrict__ wa, const float* __restrict__ ba,
    const float* __restrict__ wb, const float* __restrict__ bb,
    const float* __restrict__ ga, const float* __restrict__ bta,
    const float* __restrict__ ma, const float* __restrict__ va,
    const float* __restrict__ gb, const float* __restrict__ btb,
    const float* __restrict__ mb, const float* __restrict__ vb,
    const float* __restrict__ attaw, const float* __restrict__ attbw)
{
    int idx = blockIdx.x * blockDim.x + threadIdx.x;
    if (idx < NOC) {
        int oc = idx;
        bool isa = oc < 64;
        int o = isa ? oc : oc - 64;
        float gamma = isa ? ga[o] : gb[o];
        float beta  = isa ? bta[o] : btb[o];
        float mean  = isa ? ma[o] : mb[o];
        float var   = isa ? va[o] : vb[o];
        float A = gamma / sqrtf(var + 1e-3f);
        float bias = isa ? ba[o] : bb[o];
        g_bfold[oc] = (bias - mean) * A + beta;
        g_attw[oc]  = isa ? attaw[o] : attbw[o];
    }
    if (idx < NSTAGE * A_FLOATS) {
        int e    = idx & 3;
        int lane = (idx >> 2) & 31;
        int blk  = (idx >> 7) & 7;
        int kc   = (idx >> 10) % 6;
        int s    = idx / A_FLOATS;
        int g    = lane >> 2;
        int tig  = lane & 3;
        int oc = blk * 16 + g + ((e & 1) ? 8 : 0);
        int kl = tig + ((e & 2) ? 4 : 0);
        int cl = (kc & 1) * 8 + kl;
        int dxi = kc >> 1;
        int cin = (s / 3) * 16 + cl;
        int dy  = s % 3;
        bool isa = oc < 64;
        int o = isa ? oc : oc - 64;
        float gamma = isa ? ga[o] : gb[o];
        float var   = isa ? va[o] : vb[o];
        float A = gamma / sqrtf(var + 1e-3f);
        const float* w = isa ? wa : wb;
        float v = w[((o * CIN + cin) * 3 + dy) * 3 + dxi] * A;
        g_wA[idx] = __uint_as_float(f2tf32(v));
    }
}

// ---------------- kernel 1: mma.sync tf32 conv + BN + 1x1 attention logit ----------------
// grid (2, 256, 4) = (col half, row y, batch). 512 threads, 16 warps, 2 CTAs/SM.
// warp w: oc0 = (w>>2)*32, pix0 = (w&3)*32. D = 128oc x 128pix, K = 24 stages x 48.
__global__ void __launch_bounds__(512, 2) conv_att_kernel(
    const float* __restrict__ x, float* __restrict__ out,
    const float* __restrict__ attaw, const float* __restrict__ attab,
    const float* __restrict__ attbw, const float* __restrict__ attbb,
    const float* __restrict__ abga, const float* __restrict__ abba,
    const float* __restrict__ abma, const float* __restrict__ abva,
    const float* __restrict__ abgb, const float* __restrict__ abbb,
    const float* __restrict__ abmb, const float* __restrict__ abvb)
{
    extern __shared__ __align__(16) char dyn[];
    const int tid  = threadIdx.x;
    const int b    = blockIdx.z;
    const int y    = blockIdx.y;
    const int c0   = blockIdx.x * 128;
    const int w    = tid >> 5;
    const int lane = tid & 31;
    const int g    = lane >> 2;
    const int tig  = lane & 3;
    const int oc0  = (w >> 2) * 32;
    const int pix0 = (w & 3) * 32;
    const int blk0 = (w >> 2) * 2;
    const uint32_t dynb = smem_u32(dyn);

    float c[2][4][4];
    #pragma unroll
    for (int mm = 0; mm < 2; mm++)
        #pragma unroll
        for (int nn = 0; nn < 4; nn++)
            #pragma unroll
            for (int k = 0; k < 4; k++) c[mm][nn][k] = 0.f;

    const int cc = tid >> 5, l32 = tid & 31;   // x staging: 16 rows x 32 threads

    // ---- prologue: stage s=0 into buffer 0 ----
    {
        const char* src = (const char*)(g_wA) + tid * 16;
        #pragma unroll
        for (int r = 0; r < 3; r++)
            cp16(dynb + AOFF(0) + tid * 16 + r * 8192, src + r * 8192);
        asm volatile("cp.async.commit_group;" ::: "memory");

        float xr[5];
        int grow = y - 1;
        if ((unsigned)grow < HH) {
            const float* xb = x + (((size_t)b * CIN + cc) * HH + grow) * WW;
            #pragma unroll
            for (int i = 0; i < 5; i++) {
                int j = l32 + i * 32;
                int col = c0 - 1 + j;
                xr[i] = (j < 130 && (unsigned)col < WW) ? xb[col] : 0.f;
            }
        } else {
            #pragma unroll
            for (int i = 0; i < 5; i++) xr[i] = 0.f;
        }
        float* Xs = (float*)(dyn + XOFF(0));
        #pragma unroll
        for (int i = 0; i < 5; i++) {
            int j = l32 + i * 32;
            if (j < 130) Xs[cc * X_STRIDE + j] = __uint_as_float(f2tf32(xr[i]));
        }
        asm volatile("cp.async.wait_group 0;" ::: "memory");
        __syncthreads();
    }

    // ---- main loop ----
    for (int s = 0; s < NSTAGE; s++) {
        const int p = s & 1;
        const bool pre = (s + 1 < NSTAGE);
        float xr[5];

        if (pre) {
            const char* src = (const char*)(g_wA + (s + 1) * A_FLOATS) + tid * 16;
            #pragma unroll
            for (int r = 0; r < 3; r++)
                cp16(dynb + AOFF(p ^ 1) + tid * 16 + r * 8192, src + r * 8192);
            asm volatile("cp.async.commit_group;" ::: "memory");
            int sn = s + 1;
            int grow = y + (sn % 3) - 1;
            if ((unsigned)grow < HH) {
                const float* xb = x + (((size_t)b * CIN + (sn / 3) * 16 + cc) * HH + grow) * WW;
                #pragma unroll
                for (int i = 0; i < 5; i++) {
                    int j = l32 + i * 32;
                    int col = c0 - 1 + j;
                    xr[i] = (j < 130 && (unsigned)col < WW) ? xb[col] : 0.f;
                }
            } else {
                #pragma unroll
                for (int i = 0; i < 5; i++) xr[i] = 0.f;
            }
        }

        // ---- compute on buffer p ----
        {
            const float4* As = (const float4*)(dyn + AOFF(p));
            const float* Xs = (const float*)(dyn + XOFF(p));
            #pragma unroll
            for (int kc = 0; kc < 6; kc++) {
                const int dxi = kc >> 1;
                const int c0k = (kc & 1) * 8;
                uint32_t a[2][4];
                #pragma unroll
                for (int mm = 0; mm < 2; mm++) {
                    float4 av = As[(kc * 8 + blk0 + mm) * 32 + lane];
                    a[mm][0] = __float_as_uint(av.x);
                    a[mm][1] = __float_as_uint(av.y);
                    a[mm][2] = __float_as_uint(av.z);
                    a[mm][3] = __float_as_uint(av.w);
                }
                #pragma unroll
                for (int nn = 0; nn < 4; nn++) {
                    const float* bp = Xs + (c0k + tig) * X_STRIDE + pix0 + nn * 8 + g + dxi;
                    uint32_t b0 = __float_as_uint(bp[0]);
                    uint32_t b1 = __float_as_uint(bp[4 * X_STRIDE]);
                    mma8(c[0][nn], a[0], b0, b1);
                    mma8(c[1][nn], a[1], b0, b1);
                }
            }
        }

        if (pre) {
            float* Xs = (float*)(dyn + XOFF(p ^ 1));
            #pragma unroll
            for (int i = 0; i < 5; i++) {
                int j = l32 + i * 32;
                if (j < 130) Xs[cc * X_STRIDE + j] = __uint_as_float(f2tf32(xr[i]));
            }
        }
        asm volatile("cp.async.wait_group 0;" ::: "memory");
        __syncthreads();
    }

    // ---------------- epilogue ----------------
    float bf[2][2], aw[2][2];
    #pragma unroll
    for (int mm = 0; mm < 2; mm++)
        #pragma unroll
        for (int i2 = 0; i2 < 2; i2++) {
            int ocr = oc0 + mm * 16 + g + i2 * 8;
            bf[mm][i2] = g_bfold[ocr];
            aw[mm][i2] = g_attw[ocr];
        }

    float ap_loc[4][2];
    #pragma unroll
    for (int nn = 0; nn < 4; nn++) { ap_loc[nn][0] = 0.f; ap_loc[nn][1] = 0.f; }

    #pragma unroll
    for (int mm = 0; mm < 2; mm++)
        #pragma unroll
        for (int i2 = 0; i2 < 2; i2++) {
            int ocr = oc0 + mm * 16 + g + i2 * 8;
            float* orow = out + (((size_t)b * NOC + ocr) * HH + y) * WW + c0 + pix0 + 2 * tig;
            #pragma unroll
            for (int nn = 0; nn < 4; nn++) {
                float f0 = c[mm][nn][i2 * 2 + 0] + bf[mm][i2];
                float f1 = c[mm][nn][i2 * 2 + 1] + bf[mm][i2];
                ap_loc[nn][0] = fmaf(aw[mm][i2], f0, ap_loc[nn][0]);
                ap_loc[nn][1] = fmaf(aw[mm][i2], f1, ap_loc[nn][1]);
                *(float2*)(orow + nn * 8) = make_float2(f0, f1);
            }
        }

    // reduce attention partials over g-lanes (same tig), deterministic butterfly
    #pragma unroll
    for (int nn = 0; nn < 4; nn++)
        #pragma unroll
        for (int j = 0; j < 2; j++) {
            float v = ap_loc[nn][j];
            v += __shfl_xor_sync(0xFFFFFFFF, v, 4);
            v += __shfl_xor_sync(0xFFFFFFFF, v, 8);
            v += __shfl_xor_sync(0xFFFFFFFF, v, 16);
            ap_loc[nn][j] = v;
        }
    float* att_part = (float*)dyn;   // [16 warps][32 pix] — A buf0 region, free now
    if (g == 0) {
        #pragma unroll
        for (int nn = 0; nn < 4; nn++) {
            att_part[w * 32 + nn * 8 + 2 * tig + 0] = ap_loc[nn][0];
            att_part[w * 32 + nn * 8 + 2 * tig + 1] = ap_loc[nn][1];
        }
    }
    __syncthreads();

    if (tid < 256) {
        int branch = tid >> 7;       // 0: a (oc 0-63 = w_oc 0,1), 1: b (w_oc 2,3)
        int pix = tid & 127;
        int wpx = pix >> 5, pl = pix & 31;
        float ssum = att_part[((2 * branch + 0) * 4 + wpx) * 32 + pl]
                   + att_part[((2 * branch + 1) * 4 + wpx) * 32 + pl];
        int xx = c0 + pix;
        float gh = fabsf((float)y  - 127.5f) * (1.f / 128.f);
        float gw = fabsf((float)xx - 127.5f) * (1.f / 128.f);
        const float* awp = branch ? attbw : attaw;
        float pre = ssum + awp[64] * gh + awp[65] * gw + (branch ? attbb[0] : attab[0]);
        float gm = branch ? abgb[0] : abga[0];
        float bt = branch ? abbb[0] : abba[0];
        float mn = branch ? abmb[0] : abma[0];
        float vr = branch ? abvb[0] : abva[0];
        float av = (pre - mn) * gm / sqrtf(vr + 1e-5f) + bt;
        g_att[(((size_t)branch * BB + b) * HH + y) * WW + xx] = av;
    }
}

// ---------------- kernel 2: 3x3 attention conv + sigmoid + in-place gating ----------------
__global__ void __launch_bounds__(256) map_kernel(
    float* __restrict__ out,
    const float* __restrict__ wa, const float* __restrict__ wb,
    const float* __restrict__ s1, const float* __restrict__ s2)
{
    __shared__ float swa[36], swb[36];
    int t = threadIdx.y * 32 + threadIdx.x;
    if (t < 36) { swa[t] = wa[t]; swb[t] = wb[t]; }
    __syncthreads();

    int b   = blockIdx.z;
    int gy  = blockIdx.y * 8 + threadIdx.y;
    int gx4 = blockIdx.x * 128 + threadIdx.x * 4;

    const float prmax = 1.41421356237f * (127.5f / 128.f);
    const float prmin = 1.41421356237f * (0.5f / 128.f);
    const float prk = 2.f / (prmax - prmin);
    const float prc = 1.f - prmax * prk;

    float scl1 = s1[0], scl2 = s2[0];
    float mapa[4], mapb[4];
    #pragma unroll
    for (int p = 0; p < 4; p++) {
        int gx = gx4 + p;
        float sa = 0.f, sb = 0.f;
        #pragma unroll
        for (int rr = 0; rr < 3; rr++) {
            int yq = gy + rr - 1;
            if ((unsigned)yq >= HH) continue;
            #pragma unroll
            for (int ss = 0; ss < 3; ss++) {
                int xq = gx + ss - 1;
                if ((unsigned)xq >= WW) continue;
                float av = g_att[(((size_t)0 * BB + b) * HH + yq) * WW + xq];
                float bv = g_att[(((size_t)1 * BB + b) * HH + yq) * WW + xq];
                float gh = fabsf((float)yq - 127.5f) * (1.f / 128.f);
                float gw = fabsf((float)xq - 127.5f) * (1.f / 128.f);
                float pr = prk * sqrtf(gh * gh + gw * gw) + prc;
                int tap = rr * 3 + ss;
                sa += swa[tap] * av + swa[9 + tap] * gh + swa[18 + tap] * gw + swa[27 + tap] * pr;
                sb += swb[tap] * bv + swb[9 + tap] * gh + swb[18 + tap] * gw + swb[27 + tap] * pr;
            }
        }
        mapa[p] = scl1 / (1.f + expf(-sa));
        mapb[p] = scl2 / (1.f + expf(-sb));
    }

    size_t base = (((size_t)b * NOC) * HH + gy) * WW + gx4;
    #pragma unroll 4
    for (int oc = 0; oc < NOC; oc++) {
        float4 v = *(float4*)(out + base + (size_t)oc * HH * WW);
        if (oc < 64) { v.x *= mapa[0]; v.y *= mapa[1]; v.z *= mapa[2]; v.w *= mapa[3]; }
        else         { v.x *= mapb[0]; v.y *= mapb[1]; v.z *= mapb[2]; v.w *= mapb[3]; }
        *(float4*)(out + base + (size_t)oc * HH * WW) = v;
    }
}

// ---------------- launch ----------------
extern "C" void kernel_launch(void* const* d_in, const int* in_sizes, int n_in,
                              void* d_out, int out_size)
{
    const float* x     = (const float*)d_in[0];
    const float* caw   = (const float*)d_in[1];
    const float* cab   = (const float*)d_in[2];
    const float* cbw   = (const float*)d_in[3];
    const float* cbb   = (const float*)d_in[4];
    const float* bag   = (const float*)d_in[5];
    const float* babt  = (const float*)d_in[6];
    const float* bam   = (const float*)d_in[7];
    const float* bav   = (const float*)d_in[8];
    const float* bbg   = (const float*)d_in[9];
    const float* bbbt  = (const float*)d_in[10];
    const float* bbm   = (const float*)d_in[11];
    const float* bbv   = (const float*)d_in[12];
    const float* attaw = (const float*)d_in[13];
    const float* attab = (const float*)d_in[14];
    const float* attbw = (const float*)d_in[15];
    const float* attbb = (const float*)d_in[16];
    const float* abga  = (const float*)d_in[17];
    const float* abba  = (const float*)d_in[18];
    const float* abma  = (const float*)d_in[19];
    const float* abva  = (const float*)d_in[20];
    const float* abgb  = (const float*)d_in[21];
    const float* abbb  = (const float*)d_in[22];
    const float* abmb  = (const float*)d_in[23];
    const float* abvb  = (const float*)d_in[24];
    const float* anaw  = (const float*)d_in[25];
    const float* anbw  = (const float*)d_in[26];
    const float* s1    = (const float*)d_in[27];
    const float* s2    = (const float*)d_in[28];
    float* out = (float*)d_out;

    cudaFuncSetAttribute(conv_att_kernel,
                         cudaFuncAttributeMaxDynamicSharedMemorySize, DYN_BYTES);

    setup_kernel<<<(NSTAGE * A_FLOATS + 255) / 256, 256>>>(
        caw, cab, cbw, cbb,
        bag, babt, bam, bav, bbg, bbbt, bbm, bbv,
        attaw, attbw);

    conv_att_kernel<<<dim3(2, HH, BB), 512, DYN_BYTES>>>(
        x, out, attaw, attab, attbw, attbb,
        abga, abba, abma, abva, abgb, abbb, abmb, abvb);

    map_kernel<<<dim3(WW / 128, HH / 8, BB), dim3(32, 8)>>>(
        out, anaw, anbw, s1, s2);
}